// round 14
// baseline (speedup 1.0000x reference)
#include <cuda_runtime.h>
#include <cuda_bf16.h>
#include <cstdint>

#define Bx 4
#define Cx 256
#define Nx 4096
#define Ex 32
#define TK 128

// Scratch (allocation-free rule: __device__ globals).
__device__ float g_g[Bx * Ex * Nx];
__device__ unsigned short g_f16h[(size_t)Bx * Nx * Ex];  // [b][n][e] hi
__device__ unsigned short g_f16l[(size_t)Bx * Nx * Ex];  // [b][n][e] lo
__device__ unsigned short g_h16h[(size_t)Bx * Ex * Nx];  // [b][e][n] hi
__device__ unsigned short g_h16l[(size_t)Bx * Ex * Nx];  // [b][e][n] lo

// ---------------------------------------------------------------------------
__device__ __forceinline__ void mma16816(float* c, const uint32_t* a,
                                         uint32_t b0, uint32_t b1)
{
    asm volatile(
        "mma.sync.aligned.m16n8k16.row.col.f32.bf16.bf16.f32 "
        "{%0,%1,%2,%3},{%4,%5,%6,%7},{%8,%9},{%0,%1,%2,%3};\n"
        : "+f"(c[0]), "+f"(c[1]), "+f"(c[2]), "+f"(c[3])
        : "r"(a[0]), "r"(a[1]), "r"(a[2]), "r"(a[3]), "r"(b0), "r"(b1));
}

__device__ __forceinline__ void ldsm4(uint32_t addr, uint32_t* r)
{
    asm volatile("ldmatrix.sync.aligned.m8n8.x4.shared.b16 {%0,%1,%2,%3}, [%4];"
                 : "=r"(r[0]), "=r"(r[1]), "=r"(r[2]), "=r"(r[3]) : "r"(addr));
}

__device__ __forceinline__ uint32_t smem_u32(const void* p)
{
    uint32_t a;
    asm("{ .reg .u64 t; cvta.to.shared.u64 t, %1; cvt.u32.u64 %0, t; }"
        : "=r"(a) : "l"(p));
    return a;
}

__device__ __forceinline__ void cpasync16(uint32_t dst, const void* src)
{
    asm volatile("cp.async.cg.shared.global [%0], [%1], 16;\n"
                 :: "r"(dst), "l"(src) : "memory");
}

__device__ __forceinline__ void cpasync_commit()
{
    asm volatile("cp.async.commit_group;\n" ::: "memory");
}

template <int N>
__device__ __forceinline__ void cpasync_wait()
{
    asm volatile("cp.async.wait_group %0;\n" :: "n"(N) : "memory");
}

__device__ __forceinline__ float ex2(float x)
{
    float y;
    asm("ex2.approx.ftz.f32 %0, %1;" : "=f"(y) : "f"(x));
    return y;
}

__device__ __forceinline__ uint32_t packbf2(float a, float b)
{
    __nv_bfloat162 t = __float22bfloat162_rn(make_float2(a, b));
    return *(uint32_t*)&t;
}

// truncation split helpers: hi = top 16 bits (exact), lo = p - hi
__device__ __forceinline__ uint32_t trunc_hi_pair(float p0, float p1)
{
    return __byte_perm(__float_as_uint(p0), __float_as_uint(p1), 0x7632);
}

__device__ __forceinline__ float trunc_lo(float p)
{
    return p - __uint_as_float(__float_as_uint(p) & 0xFFFF0000u);
}

// ===========================================================================
// Kernel 1: f/g/h = W @ x + b.  grid (32, B, 3), block 256.  [measured best]
// ===========================================================================
__global__ __launch_bounds__(256) void proj_kernel(
    const float* __restrict__ x,
    const float* __restrict__ Wk, const float* __restrict__ bk,
    const float* __restrict__ Wq, const float* __restrict__ bq,
    const float* __restrict__ Wv, const float* __restrict__ bv)
{
    const int tid = threadIdx.x;
    const int tl  = tid & 31;
    const int es  = tid >> 5;
    const int n0  = blockIdx.x * 128 + tl * 4;
    const int b   = blockIdx.y;
    const int z   = blockIdx.z;

    const float* W;
    const float* bias;
    if (z == 0)      { W = Wk; bias = bk; }
    else if (z == 1) { W = Wq; bias = bq; }
    else             { W = Wv; bias = bv; }

    const float* xp = x + (size_t)b * Cx * Nx + n0;
    const int e0 = es * 4;

    float acc[4][4];
#pragma unroll
    for (int e = 0; e < 4; e++) {
        const float bv0 = bias[e0 + e];
#pragma unroll
        for (int t = 0; t < 4; t++) acc[e][t] = bv0;
    }

    const float4* W4 = (const float4*)W;  // [Ex][Cx/4]

    float4 xa[4], xb[4];
#pragma unroll
    for (int j = 0; j < 4; j++)
        xa[j] = *(const float4*)&xp[j * Nx];

#pragma unroll 1
    for (int c4 = 0; c4 < Cx / 4; c4 += 2) {
#pragma unroll
        for (int j = 0; j < 4; j++)
            xb[j] = *(const float4*)&xp[((c4 + 1) * 4 + j) * Nx];
#pragma unroll
        for (int e = 0; e < 4; e++) {
            const float4 w = W4[(e0 + e) * (Cx / 4) + c4];
            acc[e][0] += w.x * xa[0].x + w.y * xa[1].x + w.z * xa[2].x + w.w * xa[3].x;
            acc[e][1] += w.x * xa[0].y + w.y * xa[1].y + w.z * xa[2].y + w.w * xa[3].y;
            acc[e][2] += w.x * xa[0].z + w.y * xa[1].z + w.z * xa[2].z + w.w * xa[3].z;
            acc[e][3] += w.x * xa[0].w + w.y * xa[1].w + w.z * xa[2].w + w.w * xa[3].w;
        }
        if (c4 + 2 < Cx / 4) {
#pragma unroll
            for (int j = 0; j < 4; j++)
                xa[j] = *(const float4*)&xp[((c4 + 2) * 4 + j) * Nx];
        }
#pragma unroll
        for (int e = 0; e < 4; e++) {
            const float4 w = W4[(e0 + e) * (Cx / 4) + c4 + 1];
            acc[e][0] += w.x * xb[0].x + w.y * xb[1].x + w.z * xb[2].x + w.w * xb[3].x;
            acc[e][1] += w.x * xb[0].y + w.y * xb[1].y + w.z * xb[2].y + w.w * xb[3].y;
            acc[e][2] += w.x * xb[0].z + w.y * xb[1].z + w.z * xb[2].z + w.w * xb[3].z;
            acc[e][3] += w.x * xb[0].w + w.y * xb[1].w + w.z * xb[2].w + w.w * xb[3].w;
        }
    }

    if (z == 1) {
#pragma unroll
        for (int e = 0; e < 4; e++)
            *(float4*)&g_g[((size_t)b * Ex + e0 + e) * Nx + n0] =
                make_float4(acc[e][0], acc[e][1], acc[e][2], acc[e][3]);
    } else if (z == 0) {
#pragma unroll
        for (int t = 0; t < 4; t++) {
            const float v0 = acc[0][t], v1 = acc[1][t];
            const float v2 = acc[2][t], v3 = acc[3][t];
            const __nv_bfloat162 h01 = __float22bfloat162_rn(make_float2(v0, v1));
            const __nv_bfloat162 h23 = __float22bfloat162_rn(make_float2(v2, v3));
            const uint32_t l01 = packbf2(v0 - __bfloat162float(h01.x),
                                         v1 - __bfloat162float(h01.y));
            const uint32_t l23 = packbf2(v2 - __bfloat162float(h23.x),
                                         v3 - __bfloat162float(h23.y));
            const size_t base = ((size_t)b * Nx + (n0 + t)) * Ex + e0;
            *(uint2*)&g_f16h[base] = make_uint2(*(const uint32_t*)&h01,
                                                *(const uint32_t*)&h23);
            *(uint2*)&g_f16l[base] = make_uint2(l01, l23);
        }
    } else {
#pragma unroll
        for (int e = 0; e < 4; e++) {
            const float v0 = acc[e][0], v1 = acc[e][1];
            const float v2 = acc[e][2], v3 = acc[e][3];
            const __nv_bfloat162 h01 = __float22bfloat162_rn(make_float2(v0, v1));
            const __nv_bfloat162 h23 = __float22bfloat162_rn(make_float2(v2, v3));
            const uint32_t l01 = packbf2(v0 - __bfloat162float(h01.x),
                                         v1 - __bfloat162float(h01.y));
            const uint32_t l23 = packbf2(v2 - __bfloat162float(h23.x),
                                         v3 - __bfloat162float(h23.y));
            const size_t base = ((size_t)b * Ex + (e0 + e)) * Nx + n0;
            *(uint2*)&g_h16h[base] = make_uint2(*(const uint32_t*)&h01,
                                                *(const uint32_t*)&h23);
            *(uint2*)&g_h16l[base] = make_uint2(l01, l23);
        }
    }
}

// ===========================================================================
// Kernel 2: flash attention + fused output projection.
// Round-14: 64 queries/block, grid (Nx/64, B) = 256 blocks, 256 threads
// (8 warps), 2 blocks/SM. warp = (qt 0..3 -> 16 queries, kh 0..1 -> 64-key
// half). Cross-BLOCK overlap hides barrier/fill stalls (round-11 per-warp
// workload, doubled block residency).
// ===========================================================================
#define FROW 80      // bytes per fh row (40 bf16)
#define HROW 272     // bytes per hh row (136 bf16)
#define BUFSZ 38912  // one tile buffer: fh|fl|hh|hl

__global__ __launch_bounds__(256, 2) void attn_mma_kernel(
    const float* __restrict__ x,
    const float* __restrict__ Wo, const float* __restrict__ bo,
    float* __restrict__ out_y, float* __restrict__ out_o,
    float* __restrict__ out_gamma)
{
    extern __shared__ __align__(128) uint8_t S[];   // 2 * BUFSZ

    const int tid  = threadIdx.x;
    const int w    = tid >> 5;
    const int lane = tid & 31;
    const int qt   = w & 3;             // 16-query tile within the 64
    const int kh   = w >> 2;            // key half
    const int b    = blockIdx.y;
    const int qw   = blockIdx.x * 64 + qt * 16;

    const float* gb = g_g + (size_t)b * Ex * Nx;
    const unsigned short* fHg = g_f16h + (size_t)b * Nx * Ex;
    const unsigned short* fLg = g_f16l + (size_t)b * Nx * Ex;
    const unsigned short* hHg = g_h16h + (size_t)b * Ex * Nx;
    const unsigned short* hLg = g_h16l + (size_t)b * Ex * Nx;

    const uint32_t sBase = smem_u32(S);
    const float LOG2E = 1.4426950408889634f;

    uint32_t gAh[2][4], gAl[2][4];
    {
        const int qa = qw + (lane >> 2);
#pragma unroll
        for (int ke = 0; ke < 2; ke++) {
#pragma unroll
            for (int r = 0; r < 4; r++) {
                const int row = qa + (r & 1) * 8;
                const int e   = ke * 16 + (r >> 1) * 8 + (lane & 3) * 2;
                const float v0 = gb[e * Nx + row] * LOG2E;
                const float v1 = gb[(e + 1) * Nx + row] * LOG2E;
                const __nv_bfloat162 hi2 = __float22bfloat162_rn(make_float2(v0, v1));
                gAh[ke][r] = *(const uint32_t*)&hi2;
                gAl[ke][r] = packbf2(v0 - __bfloat162float(hi2.x),
                                     v1 - __bfloat162float(hi2.y));
            }
        }
    }

    float Vac[4][4];
#pragma unroll
    for (int nt = 0; nt < 4; nt++)
#pragma unroll
        for (int r = 0; r < 4; r++) Vac[nt][r] = 0.f;
    float lsum0 = 0.f, lsum1 = 0.f;

    const int m = lane >> 3;
    const uint32_t fSel = (uint32_t)(((m >> 1) * 8 + (lane & 7)) * FROW + (m & 1) * 16);
    const uint32_t hSel = (uint32_t)(((m >> 1) * 8 + (lane & 7)) * HROW + (m & 1) * 16);

    // per-thread fill roles (256 threads, 2 x 16B chunks per array each)
    const int fk  = tid >> 1, fc0 = (tid & 1) * 2;        // f: row, chunk pair
    const int he  = tid >> 3, hc0 = (tid & 7) * 2;        // h: row, chunk pair
    const uint32_t fOff0 = (uint32_t)(fk * FROW + fc0 * 16);
    const uint32_t hOff0 = (uint32_t)(he * HROW + hc0 * 16);

    // issue fill for tile 0 into buffer 0
#pragma unroll
    for (int c = 0; c < 2; c++) {
        cpasync16(sBase + fOff0 + c * 16,         fHg + (size_t)fk * Ex + (fc0 + c) * 8);
        cpasync16(sBase + 10240 + fOff0 + c * 16, fLg + (size_t)fk * Ex + (fc0 + c) * 8);
        cpasync16(sBase + 20480 + hOff0 + c * 16, hHg + (size_t)he * Nx + (hc0 + c) * 8);
        cpasync16(sBase + 29184 + hOff0 + c * 16, hLg + (size_t)he * Nx + (hc0 + c) * 8);
    }
    cpasync_commit();

#pragma unroll 1
    for (int t = 0; t < Nx / TK; t++) {
        const uint32_t cbuf = sBase + (uint32_t)(t & 1) * BUFSZ;

        if (t + 1 < Nx / TK) {
            const uint32_t nbuf = sBase + (uint32_t)((t + 1) & 1) * BUFSZ;
            const int i1 = (t + 1) * TK;
#pragma unroll
            for (int c = 0; c < 2; c++) {
                cpasync16(nbuf + fOff0 + c * 16,
                          fHg + (size_t)(i1 + fk) * Ex + (fc0 + c) * 8);
                cpasync16(nbuf + 10240 + fOff0 + c * 16,
                          fLg + (size_t)(i1 + fk) * Ex + (fc0 + c) * 8);
                cpasync16(nbuf + 20480 + hOff0 + c * 16,
                          hHg + (size_t)he * Nx + i1 + (hc0 + c) * 8);
                cpasync16(nbuf + 29184 + hOff0 + c * 16,
                          hLg + (size_t)he * Nx + i1 + (hc0 + c) * 8);
            }
            cpasync_commit();
            cpasync_wait<1>();
        } else {
            cpasync_wait<0>();
        }
        __syncthreads();

        const uint32_t fhA = cbuf, flA = cbuf + 10240;
        const uint32_t hhA = cbuf + 20480, hlA = cbuf + 29184;

#pragma unroll 1
        for (int kk = 0; kk < 4; kk++) {        // this warp's 64-key half
            const uint32_t fTile = (uint32_t)((kh * 64 + kk * 16) * FROW) + fSel;
            float c0a[4] = {0.f, 0.f, 0.f, 0.f};
            float c0b[4] = {0.f, 0.f, 0.f, 0.f};
            float c1a[4] = {0.f, 0.f, 0.f, 0.f};
            float c1b[4] = {0.f, 0.f, 0.f, 0.f};

#pragma unroll
            for (int ke = 0; ke < 2; ke++) {
                uint32_t bh[4], bl[4];
                ldsm4(fhA + fTile + ke * 32, bh);
                ldsm4(flA + fTile + ke * 32, bl);
                mma16816(c0a, gAh[ke], bh[0], bh[1]);
                mma16816(c1a, gAh[ke], bh[2], bh[3]);
                mma16816(c0b, gAl[ke], bh[0], bh[1]);
                mma16816(c1b, gAl[ke], bh[2], bh[3]);
                mma16816(c0b, gAh[ke], bl[0], bl[1]);
                mma16816(c1b, gAh[ke], bl[2], bl[3]);
            }

            float p0[4], p1[4];
#pragma unroll
            for (int r = 0; r < 4; r++) {
                p0[r] = ex2(c0a[r] + c0b[r]);
                p1[r] = ex2(c1a[r] + c1b[r]);
            }
            lsum0 += (p0[0] + p0[1]) + (p1[0] + p1[1]);
            lsum1 += (p0[2] + p0[3]) + (p1[2] + p1[3]);

            uint32_t aPh[4], aPl[4];
            aPh[0] = trunc_hi_pair(p0[0], p0[1]);
            aPh[1] = trunc_hi_pair(p0[2], p0[3]);
            aPh[2] = trunc_hi_pair(p1[0], p1[1]);
            aPh[3] = trunc_hi_pair(p1[2], p1[3]);
            aPl[0] = packbf2(trunc_lo(p0[0]), trunc_lo(p0[1]));
            aPl[1] = packbf2(trunc_lo(p0[2]), trunc_lo(p0[3]));
            aPl[2] = packbf2(trunc_lo(p1[0]), trunc_lo(p1[1]));
            aPl[3] = packbf2(trunc_lo(p1[2]), trunc_lo(p1[3]));

            const uint32_t hTile = (uint32_t)(kh * 128 + kk * 32) + hSel;
            uint32_t b0[4], b1[4], d0[4], d1[4];
            ldsm4(hhA + hTile, b0);
            ldsm4(hhA + hTile + 16 * HROW, b1);
            ldsm4(hlA + hTile, d0);
            ldsm4(hlA + hTile + 16 * HROW, d1);
#pragma unroll
            for (int j = 0; j < 2; j++) {
                mma16816(Vac[j],   aPh, b0[2*j], b0[2*j+1]);
                mma16816(Vac[j],   aPl, b0[2*j], b0[2*j+1]);
                mma16816(Vac[j],   aPh, d0[2*j], d0[2*j+1]);
                mma16816(Vac[2+j], aPh, b1[2*j], b1[2*j+1]);
                mma16816(Vac[2+j], aPl, b1[2*j], b1[2*j+1]);
                mma16816(Vac[2+j], aPh, d1[2*j], d1[2*j+1]);
            }
        }
        __syncthreads();
    }

    // ---- combine the two key-halves (smem), normalize, stage v ----
    float* Vbuf = (float*)S;               // [64][33] floats  (8448 B)
    float* Lbuf = (float*)(S + 8704);      // 64 floats

    lsum0 += __shfl_xor_sync(0xffffffffu, lsum0, 1);
    lsum0 += __shfl_xor_sync(0xffffffffu, lsum0, 2);
    lsum1 += __shfl_xor_sync(0xffffffffu, lsum1, 1);
    lsum1 += __shfl_xor_sync(0xffffffffu, lsum1, 2);

    const int qrow = lane >> 2;
    const int row0 = qt * 16 + qrow;
    if (kh == 1) {
#pragma unroll
        for (int nt = 0; nt < 4; nt++) {
            const int e = nt * 8 + (lane & 3) * 2;
            Vbuf[row0 * 33 + e]           = Vac[nt][0];
            Vbuf[row0 * 33 + e + 1]       = Vac[nt][1];
            Vbuf[(row0 + 8) * 33 + e]     = Vac[nt][2];
            Vbuf[(row0 + 8) * 33 + e + 1] = Vac[nt][3];
        }
        if ((lane & 3) == 0) {
            Lbuf[row0]     = lsum0;
            Lbuf[row0 + 8] = lsum1;
        }
    }
    __syncthreads();
    if (kh == 0) {
        const float inv0 = 1.0f / (lsum0 + Lbuf[row0]);
        const float inv1 = 1.0f / (lsum1 + Lbuf[row0 + 8]);
#pragma unroll
        for (int nt = 0; nt < 4; nt++) {
            const int e = nt * 8 + (lane & 3) * 2;
            float* r0 = &Vbuf[row0 * 33 + e];
            float* r1 = &Vbuf[(row0 + 8) * 33 + e];
            r0[0] = (Vac[nt][0] + r0[0]) * inv0;
            r0[1] = (Vac[nt][1] + r0[1]) * inv0;
            r1[0] = (Vac[nt][2] + r1[0]) * inv1;
            r1[1] = (Vac[nt][3] + r1[1]) * inv1;
        }
    }
    __syncthreads();

    // ---- fused output projection: o = Wo v + bo ; y = 0.5 o + x ----
    {
        const int token = tid & 63;
        const int cs    = tid >> 6;          // 0..3, warp-uniform
        const int q     = blockIdx.x * 64 + token;

        float vr[Ex];
#pragma unroll
        for (int e = 0; e < Ex; e++) vr[e] = Vbuf[token * 33 + e];

        const float4* Wo4 = (const float4*)Wo;   // [Cx][Ex/4]
        const float* xp = x + (size_t)b * Cx * Nx + q;
        float* yp = out_y + (size_t)b * Cx * Nx + q;
        float* op = out_o ? (out_o + (size_t)b * Cx * Nx + q) : nullptr;

        const int c0 = cs * 64;
#pragma unroll 4
        for (int ci = 0; ci < 64; ci++) {
            const int c = c0 + ci;
            float a = bo[c];
#pragma unroll
            for (int e4 = 0; e4 < Ex / 4; e4++) {
                const float4 wv = Wo4[c * (Ex / 4) + e4];
                a += wv.x * vr[e4*4+0] + wv.y * vr[e4*4+1] +
                     wv.z * vr[e4*4+2] + wv.w * vr[e4*4+3];
            }
            if (op) op[c * Nx] = a;
            yp[c * Nx] = 0.5f * a + xp[c * Nx];
        }
    }

    if (out_gamma && blockIdx.x == 0 && blockIdx.y == 0 && tid == 0)
        out_gamma[0] = 0.5f;
}

// ===========================================================================
extern "C" void kernel_launch(void* const* d_in, const int* in_sizes, int n_in,
                              void* d_out, int out_size)
{
    const float* x  = (const float*)d_in[0];
    const float* Wk = (const float*)d_in[1];
    const float* bk = (const float*)d_in[2];
    const float* Wq = (const float*)d_in[3];
    const float* bq = (const float*)d_in[4];
    const float* Wv = (const float*)d_in[5];
    const float* bv = (const float*)d_in[6];
    const float* Wo = (const float*)d_in[7];
    const float* bo = (const float*)d_in[8];

    const size_t BCN = (size_t)Bx * Cx * Nx;  // 4194304
    float* out = (float*)d_out;

    const bool full = ((size_t)out_size >= 2 * BCN + 1);
    float* out_y = out;
    float* out_o = full ? (out + BCN) : nullptr;
    float* out_g = full ? (out + 2 * BCN) : nullptr;

    static bool attr_set = false;
    if (!attr_set) {
        cudaFuncSetAttribute(attn_mma_kernel,
                             cudaFuncAttributeMaxDynamicSharedMemorySize,
                             2 * BUFSZ);
        attr_set = true;
    }

    proj_kernel<<<dim3(Nx / 128, Bx, 3), 256>>>(x, Wk, bk, Wq, bq, Wv, bv);
    attn_mma_kernel<<<dim3(Nx / 64, Bx), 256, 2 * BUFSZ>>>(
        x, Wo, bo, out_y, out_o, out_g);
}

// round 15
// speedup vs baseline: 1.1041x; 1.1041x over previous
#include <cuda_runtime.h>
#include <cuda_bf16.h>
#include <cstdint>

#define Bx 4
#define Cx 256
#define Nx 4096
#define Ex 32
#define TK 128

// Scratch (allocation-free rule: __device__ globals).
__device__ float g_g[Bx * Ex * Nx];
__device__ unsigned short g_f16h[(size_t)Bx * Nx * Ex];  // [b][n][e] hi
__device__ unsigned short g_f16l[(size_t)Bx * Nx * Ex];  // [b][n][e] lo
__device__ unsigned short g_h16h[(size_t)Bx * Ex * Nx];  // [b][e][n] hi
__device__ unsigned short g_h16l[(size_t)Bx * Ex * Nx];  // [b][e][n] lo

// ---------------------------------------------------------------------------
__device__ __forceinline__ void mma16816(float* c, const uint32_t* a,
                                         uint32_t b0, uint32_t b1)
{
    asm volatile(
        "mma.sync.aligned.m16n8k16.row.col.f32.bf16.bf16.f32 "
        "{%0,%1,%2,%3},{%4,%5,%6,%7},{%8,%9},{%0,%1,%2,%3};\n"
        : "+f"(c[0]), "+f"(c[1]), "+f"(c[2]), "+f"(c[3])
        : "r"(a[0]), "r"(a[1]), "r"(a[2]), "r"(a[3]), "r"(b0), "r"(b1));
}

__device__ __forceinline__ void ldsm4(uint32_t addr, uint32_t* r)
{
    asm volatile("ldmatrix.sync.aligned.m8n8.x4.shared.b16 {%0,%1,%2,%3}, [%4];"
                 : "=r"(r[0]), "=r"(r[1]), "=r"(r[2]), "=r"(r[3]) : "r"(addr));
}

__device__ __forceinline__ uint32_t smem_u32(const void* p)
{
    uint32_t a;
    asm("{ .reg .u64 t; cvta.to.shared.u64 t, %1; cvt.u32.u64 %0, t; }"
        : "=r"(a) : "l"(p));
    return a;
}

__device__ __forceinline__ void cpasync16(uint32_t dst, const void* src)
{
    asm volatile("cp.async.cg.shared.global [%0], [%1], 16;\n"
                 :: "r"(dst), "l"(src) : "memory");
}

__device__ __forceinline__ void cpasync_commit()
{
    asm volatile("cp.async.commit_group;\n" ::: "memory");
}

template <int N>
__device__ __forceinline__ void cpasync_wait()
{
    asm volatile("cp.async.wait_group %0;\n" :: "n"(N) : "memory");
}

__device__ __forceinline__ float ex2(float x)
{
    float y;
    asm("ex2.approx.ftz.f32 %0, %1;" : "=f"(y) : "f"(x));
    return y;
}

__device__ __forceinline__ uint32_t packbf2(float a, float b)
{
    __nv_bfloat162 t = __float22bfloat162_rn(make_float2(a, b));
    return *(uint32_t*)&t;
}

// truncation split helpers: hi = top 16 bits (exact), lo = p - hi
__device__ __forceinline__ uint32_t trunc_hi_pair(float p0, float p1)
{
    return __byte_perm(__float_as_uint(p0), __float_as_uint(p1), 0x7632);
}

__device__ __forceinline__ float trunc_lo(float p)
{
    return p - __uint_as_float(__float_as_uint(p) & 0xFFFF0000u);
}

// ===========================================================================
// Kernel 1: f/g/h = W @ x + b.  grid (32, B, 3), block 256.  [measured best]
// ===========================================================================
__global__ __launch_bounds__(256) void proj_kernel(
    const float* __restrict__ x,
    const float* __restrict__ Wk, const float* __restrict__ bk,
    const float* __restrict__ Wq, const float* __restrict__ bq,
    const float* __restrict__ Wv, const float* __restrict__ bv)
{
    const int tid = threadIdx.x;
    const int tl  = tid & 31;
    const int es  = tid >> 5;
    const int n0  = blockIdx.x * 128 + tl * 4;
    const int b   = blockIdx.y;
    const int z   = blockIdx.z;

    const float* W;
    const float* bias;
    if (z == 0)      { W = Wk; bias = bk; }
    else if (z == 1) { W = Wq; bias = bq; }
    else             { W = Wv; bias = bv; }

    const float* xp = x + (size_t)b * Cx * Nx + n0;
    const int e0 = es * 4;

    float acc[4][4];
#pragma unroll
    for (int e = 0; e < 4; e++) {
        const float bv0 = bias[e0 + e];
#pragma unroll
        for (int t = 0; t < 4; t++) acc[e][t] = bv0;
    }

    const float4* W4 = (const float4*)W;  // [Ex][Cx/4]

    float4 xa[4], xb[4];
#pragma unroll
    for (int j = 0; j < 4; j++)
        xa[j] = *(const float4*)&xp[j * Nx];

#pragma unroll 1
    for (int c4 = 0; c4 < Cx / 4; c4 += 2) {
#pragma unroll
        for (int j = 0; j < 4; j++)
            xb[j] = *(const float4*)&xp[((c4 + 1) * 4 + j) * Nx];
#pragma unroll
        for (int e = 0; e < 4; e++) {
            const float4 w = W4[(e0 + e) * (Cx / 4) + c4];
            acc[e][0] += w.x * xa[0].x + w.y * xa[1].x + w.z * xa[2].x + w.w * xa[3].x;
            acc[e][1] += w.x * xa[0].y + w.y * xa[1].y + w.z * xa[2].y + w.w * xa[3].y;
            acc[e][2] += w.x * xa[0].z + w.y * xa[1].z + w.z * xa[2].z + w.w * xa[3].z;
            acc[e][3] += w.x * xa[0].w + w.y * xa[1].w + w.z * xa[2].w + w.w * xa[3].w;
        }
        if (c4 + 2 < Cx / 4) {
#pragma unroll
            for (int j = 0; j < 4; j++)
                xa[j] = *(const float4*)&xp[((c4 + 2) * 4 + j) * Nx];
        }
#pragma unroll
        for (int e = 0; e < 4; e++) {
            const float4 w = W4[(e0 + e) * (Cx / 4) + c4 + 1];
            acc[e][0] += w.x * xb[0].x + w.y * xb[1].x + w.z * xb[2].x + w.w * xb[3].x;
            acc[e][1] += w.x * xb[0].y + w.y * xb[1].y + w.z * xb[2].y + w.w * xb[3].y;
            acc[e][2] += w.x * xb[0].z + w.y * xb[1].z + w.z * xb[2].z + w.w * xb[3].z;
            acc[e][3] += w.x * xb[0].w + w.y * xb[1].w + w.z * xb[2].w + w.w * xb[3].w;
        }
    }

    if (z == 1) {
#pragma unroll
        for (int e = 0; e < 4; e++)
            *(float4*)&g_g[((size_t)b * Ex + e0 + e) * Nx + n0] =
                make_float4(acc[e][0], acc[e][1], acc[e][2], acc[e][3]);
    } else if (z == 0) {
#pragma unroll
        for (int t = 0; t < 4; t++) {
            const float v0 = acc[0][t], v1 = acc[1][t];
            const float v2 = acc[2][t], v3 = acc[3][t];
            const __nv_bfloat162 h01 = __float22bfloat162_rn(make_float2(v0, v1));
            const __nv_bfloat162 h23 = __float22bfloat162_rn(make_float2(v2, v3));
            const uint32_t l01 = packbf2(v0 - __bfloat162float(h01.x),
                                         v1 - __bfloat162float(h01.y));
            const uint32_t l23 = packbf2(v2 - __bfloat162float(h23.x),
                                         v3 - __bfloat162float(h23.y));
            const size_t base = ((size_t)b * Nx + (n0 + t)) * Ex + e0;
            *(uint2*)&g_f16h[base] = make_uint2(*(const uint32_t*)&h01,
                                                *(const uint32_t*)&h23);
            *(uint2*)&g_f16l[base] = make_uint2(l01, l23);
        }
    } else {
#pragma unroll
        for (int e = 0; e < 4; e++) {
            const float v0 = acc[e][0], v1 = acc[e][1];
            const float v2 = acc[e][2], v3 = acc[e][3];
            const __nv_bfloat162 h01 = __float22bfloat162_rn(make_float2(v0, v1));
            const __nv_bfloat162 h23 = __float22bfloat162_rn(make_float2(v2, v3));
            const uint32_t l01 = packbf2(v0 - __bfloat162float(h01.x),
                                         v1 - __bfloat162float(h01.y));
            const uint32_t l23 = packbf2(v2 - __bfloat162float(h23.x),
                                         v3 - __bfloat162float(h23.y));
            const size_t base = ((size_t)b * Ex + (e0 + e)) * Nx + n0;
            *(uint2*)&g_h16h[base] = make_uint2(*(const uint32_t*)&h01,
                                                *(const uint32_t*)&h23);
            *(uint2*)&g_h16l[base] = make_uint2(l01, l23);
        }
    }
}

// ===========================================================================
// Kernel 2: flash attention + fused output projection.
// Round-15: round-12 structure (512 thr, 16 warps, kh split, cp.async
// double buffer, fused oproj) with the kk loop at unroll 2 so S'(kk+1)
// MMAs overlap epilogue(kk)'s ex2/pack chain.
// ===========================================================================
#define FROW 80      // bytes per fh row (40 bf16)
#define HROW 272     // bytes per hh row (136 bf16)
#define BUFSZ 38912  // one tile buffer: fh|fl|hh|hl

__global__ __launch_bounds__(512, 1) void attn_mma_kernel(
    const float* __restrict__ x,
    const float* __restrict__ Wo, const float* __restrict__ bo,
    float* __restrict__ out_y, float* __restrict__ out_o,
    float* __restrict__ out_gamma)
{
    extern __shared__ __align__(128) uint8_t S[];   // 2 * BUFSZ

    const int tid  = threadIdx.x;
    const int w    = tid >> 5;
    const int lane = tid & 31;
    const int qt   = w & 7;
    const int kh   = w >> 3;
    const int b    = blockIdx.y;
    const int qw   = blockIdx.x * 128 + qt * 16;

    const float* gb = g_g + (size_t)b * Ex * Nx;
    const unsigned short* fHg = g_f16h + (size_t)b * Nx * Ex;
    const unsigned short* fLg = g_f16l + (size_t)b * Nx * Ex;
    const unsigned short* hHg = g_h16h + (size_t)b * Ex * Nx;
    const unsigned short* hLg = g_h16l + (size_t)b * Ex * Nx;

    const uint32_t sBase = smem_u32(S);
    const float LOG2E = 1.4426950408889634f;

    uint32_t gAh[2][4], gAl[2][4];
    {
        const int qa = qw + (lane >> 2);
#pragma unroll
        for (int ke = 0; ke < 2; ke++) {
#pragma unroll
            for (int r = 0; r < 4; r++) {
                const int row = qa + (r & 1) * 8;
                const int e   = ke * 16 + (r >> 1) * 8 + (lane & 3) * 2;
                const float v0 = gb[e * Nx + row] * LOG2E;
                const float v1 = gb[(e + 1) * Nx + row] * LOG2E;
                const __nv_bfloat162 hi2 = __float22bfloat162_rn(make_float2(v0, v1));
                gAh[ke][r] = *(const uint32_t*)&hi2;
                gAl[ke][r] = packbf2(v0 - __bfloat162float(hi2.x),
                                     v1 - __bfloat162float(hi2.y));
            }
        }
    }

    float Vac[4][4];
#pragma unroll
    for (int nt = 0; nt < 4; nt++)
#pragma unroll
        for (int r = 0; r < 4; r++) Vac[nt][r] = 0.f;
    float lsum0 = 0.f, lsum1 = 0.f;

    const int m = lane >> 3;
    const uint32_t fSel = (uint32_t)(((m >> 1) * 8 + (lane & 7)) * FROW + (m & 1) * 16);
    const uint32_t hSel = (uint32_t)(((m >> 1) * 8 + (lane & 7)) * HROW + (m & 1) * 16);

    // per-thread fill roles
    const int fk = tid >> 2, fch = tid & 3;
    const int he = tid >> 4, hkc = (tid & 15) * 8;
    const uint32_t fOff = (uint32_t)(fk * FROW + fch * 16);
    const uint32_t hOff = (uint32_t)(he * HROW + hkc * 2);

    // issue fill for tile 0 into buffer 0
    {
        cpasync16(sBase + fOff,         fHg + (size_t)fk * Ex + fch * 8);
        cpasync16(sBase + 10240 + fOff, fLg + (size_t)fk * Ex + fch * 8);
        cpasync16(sBase + 20480 + hOff, hHg + (size_t)he * Nx + hkc);
        cpasync16(sBase + 29184 + hOff, hLg + (size_t)he * Nx + hkc);
        cpasync_commit();
    }

#pragma unroll 1
    for (int t = 0; t < Nx / TK; t++) {
        const uint32_t cbuf = sBase + (uint32_t)(t & 1) * BUFSZ;

        if (t + 1 < Nx / TK) {
            const uint32_t nbuf = sBase + (uint32_t)((t + 1) & 1) * BUFSZ;
            const int i1 = (t + 1) * TK;
            cpasync16(nbuf + fOff,         fHg + (size_t)(i1 + fk) * Ex + fch * 8);
            cpasync16(nbuf + 10240 + fOff, fLg + (size_t)(i1 + fk) * Ex + fch * 8);
            cpasync16(nbuf + 20480 + hOff, hHg + (size_t)he * Nx + i1 + hkc);
            cpasync16(nbuf + 29184 + hOff, hLg + (size_t)he * Nx + i1 + hkc);
            cpasync_commit();
            cpasync_wait<1>();
        } else {
            cpasync_wait<0>();
        }
        __syncthreads();

        const uint32_t fhA = cbuf, flA = cbuf + 10240;
        const uint32_t hhA = cbuf + 20480, hlA = cbuf + 29184;

#pragma unroll 2
        for (int kk = 0; kk < 4; kk++) {
            const uint32_t fTile = (uint32_t)((kh * 64 + kk * 16) * FROW) + fSel;
            // two independent accumulation chains per C half
            float c0a[4] = {0.f, 0.f, 0.f, 0.f};
            float c0b[4] = {0.f, 0.f, 0.f, 0.f};
            float c1a[4] = {0.f, 0.f, 0.f, 0.f};
            float c1b[4] = {0.f, 0.f, 0.f, 0.f};

#pragma unroll
            for (int ke = 0; ke < 2; ke++) {
                uint32_t bh[4], bl[4];
                ldsm4(fhA + fTile + ke * 32, bh);
                ldsm4(flA + fTile + ke * 32, bl);
                mma16816(c0a, gAh[ke], bh[0], bh[1]);   // chain A (depth 2)
                mma16816(c1a, gAh[ke], bh[2], bh[3]);
                mma16816(c0b, gAl[ke], bh[0], bh[1]);   // chain B (depth 4)
                mma16816(c1b, gAl[ke], bh[2], bh[3]);
                mma16816(c0b, gAh[ke], bl[0], bl[1]);
                mma16816(c1b, gAh[ke], bl[2], bl[3]);
            }

            float p0[4], p1[4];
#pragma unroll
            for (int r = 0; r < 4; r++) {
                p0[r] = ex2(c0a[r] + c0b[r]);
                p1[r] = ex2(c1a[r] + c1b[r]);
            }
            lsum0 += (p0[0] + p0[1]) + (p1[0] + p1[1]);
            lsum1 += (p0[2] + p0[3]) + (p1[2] + p1[3]);

            // truncation split: hi via PRMT (exact, 1 op), lo = p - hi
            uint32_t aPh[4], aPl[4];
            aPh[0] = trunc_hi_pair(p0[0], p0[1]);
            aPh[1] = trunc_hi_pair(p0[2], p0[3]);
            aPh[2] = trunc_hi_pair(p1[0], p1[1]);
            aPh[3] = trunc_hi_pair(p1[2], p1[3]);
            aPl[0] = packbf2(trunc_lo(p0[0]), trunc_lo(p0[1]));
            aPl[1] = packbf2(trunc_lo(p0[2]), trunc_lo(p0[3]));
            aPl[2] = packbf2(trunc_lo(p1[0]), trunc_lo(p1[1]));
            aPl[3] = packbf2(trunc_lo(p1[2]), trunc_lo(p1[3]));

            const uint32_t hTile = (uint32_t)(kh * 128 + kk * 32) + hSel;
            uint32_t b0[4], b1[4], d0[4], d1[4];
            ldsm4(hhA + hTile, b0);
            ldsm4(hhA + hTile + 16 * HROW, b1);
            ldsm4(hlA + hTile, d0);
            ldsm4(hlA + hTile + 16 * HROW, d1);
#pragma unroll
            for (int j = 0; j < 2; j++) {
                mma16816(Vac[j],   aPh, b0[2*j], b0[2*j+1]);
                mma16816(Vac[j],   aPl, b0[2*j], b0[2*j+1]);
                mma16816(Vac[j],   aPh, d0[2*j], d0[2*j+1]);
                mma16816(Vac[2+j], aPh, b1[2*j], b1[2*j+1]);
                mma16816(Vac[2+j], aPl, b1[2*j], b1[2*j+1]);
                mma16816(Vac[2+j], aPh, d1[2*j], d1[2*j+1]);
            }
        }
        __syncthreads();
    }

    // ---- combine halves, normalize, leave v in smem ----
    float* Vbuf = (float*)S;               // [128][33] floats
    float* Lbuf = (float*)(S + 17408);     // 128 floats

    lsum0 += __shfl_xor_sync(0xffffffffu, lsum0, 1);
    lsum0 += __shfl_xor_sync(0xffffffffu, lsum0, 2);
    lsum1 += __shfl_xor_sync(0xffffffffu, lsum1, 1);
    lsum1 += __shfl_xor_sync(0xffffffffu, lsum1, 2);

    const int qrow = lane >> 2;
    if (kh == 1) {
#pragma unroll
        for (int nt = 0; nt < 4; nt++) {
            const int e = nt * 8 + (lane & 3) * 2;
            Vbuf[(qt * 16 + qrow) * 33 + e]         = Vac[nt][0];
            Vbuf[(qt * 16 + qrow) * 33 + e + 1]     = Vac[nt][1];
            Vbuf[(qt * 16 + qrow + 8) * 33 + e]     = Vac[nt][2];
            Vbuf[(qt * 16 + qrow + 8) * 33 + e + 1] = Vac[nt][3];
        }
        if ((lane & 3) == 0) {
            Lbuf[qt * 16 + qrow]     = lsum0;
            Lbuf[qt * 16 + qrow + 8] = lsum1;
        }
    }
    __syncthreads();
    if (kh == 0) {
        const float inv0 = 1.0f / (lsum0 + Lbuf[qt * 16 + qrow]);
        const float inv1 = 1.0f / (lsum1 + Lbuf[qt * 16 + qrow + 8]);
#pragma unroll
        for (int nt = 0; nt < 4; nt++) {
            const int e = nt * 8 + (lane & 3) * 2;
            float* r0 = &Vbuf[(qt * 16 + qrow) * 33 + e];
            float* r1 = &Vbuf[(qt * 16 + qrow + 8) * 33 + e];
            r0[0] = (Vac[nt][0] + r0[0]) * inv0;
            r0[1] = (Vac[nt][1] + r0[1]) * inv0;
            r1[0] = (Vac[nt][2] + r1[0]) * inv1;
            r1[1] = (Vac[nt][3] + r1[1]) * inv1;
        }
    }
    __syncthreads();

    // ---- fused output projection: o = Wo v + bo ; y = 0.5 o + x ----
    {
        const int token = tid & 127;
        const int cs    = tid >> 7;          // 0..3, warp-uniform
        const int q     = blockIdx.x * 128 + token;

        float vr[Ex];
#pragma unroll
        for (int e = 0; e < Ex; e++) vr[e] = Vbuf[token * 33 + e];

        const float4* Wo4 = (const float4*)Wo;   // [Cx][Ex/4]
        const float* xp = x + (size_t)b * Cx * Nx + q;
        float* yp = out_y + (size_t)b * Cx * Nx + q;
        float* op = out_o ? (out_o + (size_t)b * Cx * Nx + q) : nullptr;

        const int c0 = cs * 64;
#pragma unroll 4
        for (int ci = 0; ci < 64; ci++) {
            const int c = c0 + ci;
            float a = bo[c];
#pragma unroll
            for (int e4 = 0; e4 < Ex / 4; e4++) {
                const float4 wv = Wo4[c * (Ex / 4) + e4];
                a += wv.x * vr[e4*4+0] + wv.y * vr[e4*4+1] +
                     wv.z * vr[e4*4+2] + wv.w * vr[e4*4+3];
            }
            if (op) op[c * Nx] = a;
            yp[c * Nx] = 0.5f * a + xp[c * Nx];
        }
    }

    if (out_gamma && blockIdx.x == 0 && blockIdx.y == 0 && tid == 0)
        out_gamma[0] = 0.5f;
}

// ===========================================================================
extern "C" void kernel_launch(void* const* d_in, const int* in_sizes, int n_in,
                              void* d_out, int out_size)
{
    const float* x  = (const float*)d_in[0];
    const float* Wk = (const float*)d_in[1];
    const float* bk = (const float*)d_in[2];
    const float* Wq = (const float*)d_in[3];
    const float* bq = (const float*)d_in[4];
    const float* Wv = (const float*)d_in[5];
    const float* bv = (const float*)d_in[6];
    const float* Wo = (const float*)d_in[7];
    const float* bo = (const float*)d_in[8];

    const size_t BCN = (size_t)Bx * Cx * Nx;  // 4194304
    float* out = (float*)d_out;

    const bool full = ((size_t)out_size >= 2 * BCN + 1);
    float* out_y = out;
    float* out_o = full ? (out + BCN) : nullptr;
    float* out_g = full ? (out + 2 * BCN) : nullptr;

    static bool attr_set = false;
    if (!attr_set) {
        cudaFuncSetAttribute(attn_mma_kernel,
                             cudaFuncAttributeMaxDynamicSharedMemorySize,
                             2 * BUFSZ);
        attr_set = true;
    }

    proj_kernel<<<dim3(Nx / 128, Bx, 3), 256>>>(x, Wk, bk, Wq, bq, Wv, bv);
    attn_mma_kernel<<<dim3(Nx / 128, Bx), 512, 2 * BUFSZ>>>(
        x, Wo, bo, out_y, out_o, out_g);
}

// round 16
// speedup vs baseline: 1.2098x; 1.0957x over previous
#include <cuda_runtime.h>
#include <cuda_bf16.h>
#include <cuda_fp16.h>
#include <cstdint>

#define Bx 4
#define Cx 256
#define Nx 4096
#define Ex 32
#define TK 128

// Scratch (allocation-free rule: __device__ globals).
__device__ float g_g[Bx * Ex * Nx];
__device__ unsigned short g_f16[(size_t)Bx * Nx * Ex];   // [b][n][e] fp16
__device__ unsigned short g_h16h[(size_t)Bx * Ex * Nx];  // [b][e][n] bf16 hi
__device__ unsigned short g_h16l[(size_t)Bx * Ex * Nx];  // [b][e][n] bf16 lo

// ---------------------------------------------------------------------------
__device__ __forceinline__ void mma_bf16(float* c, const uint32_t* a,
                                         uint32_t b0, uint32_t b1)
{
    asm volatile(
        "mma.sync.aligned.m16n8k16.row.col.f32.bf16.bf16.f32 "
        "{%0,%1,%2,%3},{%4,%5,%6,%7},{%8,%9},{%0,%1,%2,%3};\n"
        : "+f"(c[0]), "+f"(c[1]), "+f"(c[2]), "+f"(c[3])
        : "r"(a[0]), "r"(a[1]), "r"(a[2]), "r"(a[3]), "r"(b0), "r"(b1));
}

__device__ __forceinline__ void mma_f16(float* c, const uint32_t* a,
                                        uint32_t b0, uint32_t b1)
{
    asm volatile(
        "mma.sync.aligned.m16n8k16.row.col.f32.f16.f16.f32 "
        "{%0,%1,%2,%3},{%4,%5,%6,%7},{%8,%9},{%0,%1,%2,%3};\n"
        : "+f"(c[0]), "+f"(c[1]), "+f"(c[2]), "+f"(c[3])
        : "r"(a[0]), "r"(a[1]), "r"(a[2]), "r"(a[3]), "r"(b0), "r"(b1));
}

__device__ __forceinline__ void ldsm4(uint32_t addr, uint32_t* r)
{
    asm volatile("ldmatrix.sync.aligned.m8n8.x4.shared.b16 {%0,%1,%2,%3}, [%4];"
                 : "=r"(r[0]), "=r"(r[1]), "=r"(r[2]), "=r"(r[3]) : "r"(addr));
}

__device__ __forceinline__ uint32_t smem_u32(const void* p)
{
    uint32_t a;
    asm("{ .reg .u64 t; cvta.to.shared.u64 t, %1; cvt.u32.u64 %0, t; }"
        : "=r"(a) : "l"(p));
    return a;
}

__device__ __forceinline__ void cpasync16(uint32_t dst, const void* src)
{
    asm volatile("cp.async.cg.shared.global [%0], [%1], 16;\n"
                 :: "r"(dst), "l"(src) : "memory");
}

__device__ __forceinline__ void cpasync_commit()
{
    asm volatile("cp.async.commit_group;\n" ::: "memory");
}

template <int N>
__device__ __forceinline__ void cpasync_wait()
{
    asm volatile("cp.async.wait_group %0;\n" :: "n"(N) : "memory");
}

__device__ __forceinline__ float ex2(float x)
{
    float y;
    asm("ex2.approx.ftz.f32 %0, %1;" : "=f"(y) : "f"(x));
    return y;
}

__device__ __forceinline__ uint32_t packbf2(float a, float b)
{
    __nv_bfloat162 t = __float22bfloat162_rn(make_float2(a, b));
    return *(uint32_t*)&t;
}

__device__ __forceinline__ uint32_t packh2(float a, float b)
{
    __half2 t = __floats2half2_rn(a, b);
    return *(uint32_t*)&t;
}

// truncation split helpers for P (bf16): hi = top 16 bits, lo = p - hi
__device__ __forceinline__ uint32_t trunc_hi_pair(float p0, float p1)
{
    return __byte_perm(__float_as_uint(p0), __float_as_uint(p1), 0x7632);
}

__device__ __forceinline__ float trunc_lo(float p)
{
    return p - __uint_as_float(__float_as_uint(p) & 0xFFFF0000u);
}

// ===========================================================================
// Kernel 1: f/g/h = W @ x + b.  grid (32, B, 3), block 256.
// f -> fp16 [b][n][32]; g -> float [b][e][n]; h -> bf16 hi/lo [b][e][n]
// ===========================================================================
__global__ __launch_bounds__(256) void proj_kernel(
    const float* __restrict__ x,
    const float* __restrict__ Wk, const float* __restrict__ bk,
    const float* __restrict__ Wq, const float* __restrict__ bq,
    const float* __restrict__ Wv, const float* __restrict__ bv)
{
    const int tid = threadIdx.x;
    const int tl  = tid & 31;
    const int es  = tid >> 5;
    const int n0  = blockIdx.x * 128 + tl * 4;
    const int b   = blockIdx.y;
    const int z   = blockIdx.z;

    const float* W;
    const float* bias;
    if (z == 0)      { W = Wk; bias = bk; }
    else if (z == 1) { W = Wq; bias = bq; }
    else             { W = Wv; bias = bv; }

    const float* xp = x + (size_t)b * Cx * Nx + n0;
    const int e0 = es * 4;

    float acc[4][4];
#pragma unroll
    for (int e = 0; e < 4; e++) {
        const float bv0 = bias[e0 + e];
#pragma unroll
        for (int t = 0; t < 4; t++) acc[e][t] = bv0;
    }

    const float4* W4 = (const float4*)W;  // [Ex][Cx/4]

    float4 xa[4], xb[4];
#pragma unroll
    for (int j = 0; j < 4; j++)
        xa[j] = *(const float4*)&xp[j * Nx];

#pragma unroll 1
    for (int c4 = 0; c4 < Cx / 4; c4 += 2) {
#pragma unroll
        for (int j = 0; j < 4; j++)
            xb[j] = *(const float4*)&xp[((c4 + 1) * 4 + j) * Nx];
#pragma unroll
        for (int e = 0; e < 4; e++) {
            const float4 w = W4[(e0 + e) * (Cx / 4) + c4];
            acc[e][0] += w.x * xa[0].x + w.y * xa[1].x + w.z * xa[2].x + w.w * xa[3].x;
            acc[e][1] += w.x * xa[0].y + w.y * xa[1].y + w.z * xa[2].y + w.w * xa[3].y;
            acc[e][2] += w.x * xa[0].z + w.y * xa[1].z + w.z * xa[2].z + w.w * xa[3].z;
            acc[e][3] += w.x * xa[0].w + w.y * xa[1].w + w.z * xa[2].w + w.w * xa[3].w;
        }
        if (c4 + 2 < Cx / 4) {
#pragma unroll
            for (int j = 0; j < 4; j++)
                xa[j] = *(const float4*)&xp[((c4 + 2) * 4 + j) * Nx];
        }
#pragma unroll
        for (int e = 0; e < 4; e++) {
            const float4 w = W4[(e0 + e) * (Cx / 4) + c4 + 1];
            acc[e][0] += w.x * xb[0].x + w.y * xb[1].x + w.z * xb[2].x + w.w * xb[3].x;
            acc[e][1] += w.x * xb[0].y + w.y * xb[1].y + w.z * xb[2].y + w.w * xb[3].y;
            acc[e][2] += w.x * xb[0].z + w.y * xb[1].z + w.z * xb[2].z + w.w * xb[3].z;
            acc[e][3] += w.x * xb[0].w + w.y * xb[1].w + w.z * xb[2].w + w.w * xb[3].w;
        }
    }

    if (z == 1) {
#pragma unroll
        for (int e = 0; e < 4; e++)
            *(float4*)&g_g[((size_t)b * Ex + e0 + e) * Nx + n0] =
                make_float4(acc[e][0], acc[e][1], acc[e][2], acc[e][3]);
    } else if (z == 0) {
        // f: [b][n][32] single fp16
#pragma unroll
        for (int t = 0; t < 4; t++) {
            const uint32_t h01 = packh2(acc[0][t], acc[1][t]);
            const uint32_t h23 = packh2(acc[2][t], acc[3][t]);
            const size_t base = ((size_t)b * Nx + (n0 + t)) * Ex + e0;
            *(uint2*)&g_f16[base] = make_uint2(h01, h23);
        }
    } else {
        // h: [b][e][n] bf16 hi/lo
#pragma unroll
        for (int e = 0; e < 4; e++) {
            const float v0 = acc[e][0], v1 = acc[e][1];
            const float v2 = acc[e][2], v3 = acc[e][3];
            const __nv_bfloat162 h01 = __float22bfloat162_rn(make_float2(v0, v1));
            const __nv_bfloat162 h23 = __float22bfloat162_rn(make_float2(v2, v3));
            const uint32_t l01 = packbf2(v0 - __bfloat162float(h01.x),
                                         v1 - __bfloat162float(h01.y));
            const uint32_t l23 = packbf2(v2 - __bfloat162float(h23.x),
                                         v3 - __bfloat162float(h23.y));
            const size_t base = ((size_t)b * Ex + (e0 + e)) * Nx + n0;
            *(uint2*)&g_h16h[base] = make_uint2(*(const uint32_t*)&h01,
                                                *(const uint32_t*)&h23);
            *(uint2*)&g_h16l[base] = make_uint2(l01, l23);
        }
    }
}

// ===========================================================================
// Kernel 2: flash attention + fused output projection.
// Round-16: S' = 2-pass fp16 (g hi/lo x f single fp16) -> 8 HMMA/kk;
// PV = 3-pass bf16 (P range requires bf16) -> 12 HMMA/kk. 20 vs 24 before.
// 512 thr, 16 warps (qt, kh), cp.async double buffer, fused oproj.
// Smem per buffer: fh 10240 | hh 8704 | hl 8704 = 27648.
// ===========================================================================
#define FROW 80      // bytes per fh row (40 fp16)
#define HROW 272     // bytes per hh row (136 bf16)
#define OFF_HH 10240
#define OFF_HL 18944
#define BUFSZ 27648

__global__ __launch_bounds__(512, 1) void attn_mma_kernel(
    const float* __restrict__ x,
    const float* __restrict__ Wo, const float* __restrict__ bo,
    float* __restrict__ out_y, float* __restrict__ out_o,
    float* __restrict__ out_gamma)
{
    extern __shared__ __align__(128) uint8_t S[];   // 2 * BUFSZ

    const int tid  = threadIdx.x;
    const int w    = tid >> 5;
    const int lane = tid & 31;
    const int qt   = w & 7;
    const int kh   = w >> 3;
    const int b    = blockIdx.y;
    const int qw   = blockIdx.x * 128 + qt * 16;

    const float* gb = g_g + (size_t)b * Ex * Nx;
    const unsigned short* fGg = g_f16 + (size_t)b * Nx * Ex;
    const unsigned short* hHg = g_h16h + (size_t)b * Ex * Nx;
    const unsigned short* hLg = g_h16l + (size_t)b * Ex * Nx;

    const uint32_t sBase = smem_u32(S);
    const float LOG2E = 1.4426950408889634f;

    // g in fp16 hi/lo (scaled by log2e)
    uint32_t gAh[2][4], gAl[2][4];
    {
        const int qa = qw + (lane >> 2);
#pragma unroll
        for (int ke = 0; ke < 2; ke++) {
#pragma unroll
            for (int r = 0; r < 4; r++) {
                const int row = qa + (r & 1) * 8;
                const int e   = ke * 16 + (r >> 1) * 8 + (lane & 3) * 2;
                const float v0 = gb[e * Nx + row] * LOG2E;
                const float v1 = gb[(e + 1) * Nx + row] * LOG2E;
                const __half h0 = __float2half_rn(v0);
                const __half h1 = __float2half_rn(v1);
                const __half2 hh2 = __halves2half2(h0, h1);
                gAh[ke][r] = *(const uint32_t*)&hh2;
                gAl[ke][r] = packh2(v0 - __half2float(h0),
                                    v1 - __half2float(h1));
            }
        }
    }

    float Vac[4][4];
#pragma unroll
    for (int nt = 0; nt < 4; nt++)
#pragma unroll
        for (int r = 0; r < 4; r++) Vac[nt][r] = 0.f;
    float lsum0 = 0.f, lsum1 = 0.f;

    const int m = lane >> 3;
    const uint32_t fSel = (uint32_t)(((m >> 1) * 8 + (lane & 7)) * FROW + (m & 1) * 16);
    const uint32_t hSel = (uint32_t)(((m >> 1) * 8 + (lane & 7)) * HROW + (m & 1) * 16);

    // per-thread fill roles (512 threads)
    const int fk = tid >> 2, fch = tid & 3;          // f: 128 rows x 4 chunks
    const int he = tid >> 4, hkc = (tid & 15) * 8;   // h: 32 rows x 16 chunks
    const uint32_t fOff = (uint32_t)(fk * FROW + fch * 16);
    const uint32_t hOff = (uint32_t)(he * HROW + hkc * 2);

    // issue fill for tile 0 into buffer 0
    {
        cpasync16(sBase + fOff,          fGg + (size_t)fk * Ex + fch * 8);
        cpasync16(sBase + OFF_HH + hOff, hHg + (size_t)he * Nx + hkc);
        cpasync16(sBase + OFF_HL + hOff, hLg + (size_t)he * Nx + hkc);
        cpasync_commit();
    }

#pragma unroll 1
    for (int t = 0; t < Nx / TK; t++) {
        const uint32_t cbuf = sBase + (uint32_t)(t & 1) * BUFSZ;

        if (t + 1 < Nx / TK) {
            const uint32_t nbuf = sBase + (uint32_t)((t + 1) & 1) * BUFSZ;
            const int i1 = (t + 1) * TK;
            cpasync16(nbuf + fOff,          fGg + (size_t)(i1 + fk) * Ex + fch * 8);
            cpasync16(nbuf + OFF_HH + hOff, hHg + (size_t)he * Nx + i1 + hkc);
            cpasync16(nbuf + OFF_HL + hOff, hLg + (size_t)he * Nx + i1 + hkc);
            cpasync_commit();
            cpasync_wait<1>();
        } else {
            cpasync_wait<0>();
        }
        __syncthreads();

        const uint32_t fhA = cbuf;
        const uint32_t hhA = cbuf + OFF_HH, hlA = cbuf + OFF_HL;

#pragma unroll 1
        for (int kk = 0; kk < 4; kk++) {
            const uint32_t fTile = (uint32_t)((kh * 64 + kk * 16) * FROW) + fSel;
            float c0a[4] = {0.f, 0.f, 0.f, 0.f};
            float c0b[4] = {0.f, 0.f, 0.f, 0.f};
            float c1a[4] = {0.f, 0.f, 0.f, 0.f};
            float c1b[4] = {0.f, 0.f, 0.f, 0.f};

            // S' : 2-pass fp16 (gh + gl) x f
#pragma unroll
            for (int ke = 0; ke < 2; ke++) {
                uint32_t bh[4];
                ldsm4(fhA + fTile + ke * 32, bh);
                mma_f16(c0a, gAh[ke], bh[0], bh[1]);
                mma_f16(c1a, gAh[ke], bh[2], bh[3]);
                mma_f16(c0b, gAl[ke], bh[0], bh[1]);
                mma_f16(c1b, gAl[ke], bh[2], bh[3]);
            }

            float p0[4], p1[4];
#pragma unroll
            for (int r = 0; r < 4; r++) {
                p0[r] = ex2(c0a[r] + c0b[r]);
                p1[r] = ex2(c1a[r] + c1b[r]);
            }
            lsum0 += (p0[0] + p0[1]) + (p1[0] + p1[1]);
            lsum1 += (p0[2] + p0[3]) + (p1[2] + p1[3]);

            // P: bf16 truncation split (range-safe)
            uint32_t aPh[4], aPl[4];
            aPh[0] = trunc_hi_pair(p0[0], p0[1]);
            aPh[1] = trunc_hi_pair(p0[2], p0[3]);
            aPh[2] = trunc_hi_pair(p1[0], p1[1]);
            aPh[3] = trunc_hi_pair(p1[2], p1[3]);
            aPl[0] = packbf2(trunc_lo(p0[0]), trunc_lo(p0[1]));
            aPl[1] = packbf2(trunc_lo(p0[2]), trunc_lo(p0[3]));
            aPl[2] = packbf2(trunc_lo(p1[0]), trunc_lo(p1[1]));
            aPl[3] = packbf2(trunc_lo(p1[2]), trunc_lo(p1[3]));

            // PV : 3-pass bf16
            const uint32_t hTile = (uint32_t)(kh * 128 + kk * 32) + hSel;
            uint32_t b0[4], b1[4], d0[4], d1[4];
            ldsm4(hhA + hTile, b0);
            ldsm4(hhA + hTile + 16 * HROW, b1);
            ldsm4(hlA + hTile, d0);
            ldsm4(hlA + hTile + 16 * HROW, d1);
#pragma unroll
            for (int j = 0; j < 2; j++) {
                mma_bf16(Vac[j],   aPh, b0[2*j], b0[2*j+1]);
                mma_bf16(Vac[j],   aPl, b0[2*j], b0[2*j+1]);
                mma_bf16(Vac[j],   aPh, d0[2*j], d0[2*j+1]);
                mma_bf16(Vac[2+j], aPh, b1[2*j], b1[2*j+1]);
                mma_bf16(Vac[2+j], aPl, b1[2*j], b1[2*j+1]);
                mma_bf16(Vac[2+j], aPh, d1[2*j], d1[2*j+1]);
            }
        }
        __syncthreads();
    }

    // ---- combine halves, normalize, leave v in smem ----
    float* Vbuf = (float*)S;               // [128][33] floats
    float* Lbuf = (float*)(S + 17408);     // 128 floats

    lsum0 += __shfl_xor_sync(0xffffffffu, lsum0, 1);
    lsum0 += __shfl_xor_sync(0xffffffffu, lsum0, 2);
    lsum1 += __shfl_xor_sync(0xffffffffu, lsum1, 1);
    lsum1 += __shfl_xor_sync(0xffffffffu, lsum1, 2);

    const int qrow = lane >> 2;
    if (kh == 1) {
#pragma unroll
        for (int nt = 0; nt < 4; nt++) {
            const int e = nt * 8 + (lane & 3) * 2;
            Vbuf[(qt * 16 + qrow) * 33 + e]         = Vac[nt][0];
            Vbuf[(qt * 16 + qrow) * 33 + e + 1]     = Vac[nt][1];
            Vbuf[(qt * 16 + qrow + 8) * 33 + e]     = Vac[nt][2];
            Vbuf[(qt * 16 + qrow + 8) * 33 + e + 1] = Vac[nt][3];
        }
        if ((lane & 3) == 0) {
            Lbuf[qt * 16 + qrow]     = lsum0;
            Lbuf[qt * 16 + qrow + 8] = lsum1;
        }
    }
    __syncthreads();
    if (kh == 0) {
        const float inv0 = 1.0f / (lsum0 + Lbuf[qt * 16 + qrow]);
        const float inv1 = 1.0f / (lsum1 + Lbuf[qt * 16 + qrow + 8]);
#pragma unroll
        for (int nt = 0; nt < 4; nt++) {
            const int e = nt * 8 + (lane & 3) * 2;
            float* r0 = &Vbuf[(qt * 16 + qrow) * 33 + e];
            float* r1 = &Vbuf[(qt * 16 + qrow + 8) * 33 + e];
            r0[0] = (Vac[nt][0] + r0[0]) * inv0;
            r0[1] = (Vac[nt][1] + r0[1]) * inv0;
            r1[0] = (Vac[nt][2] + r1[0]) * inv1;
            r1[1] = (Vac[nt][3] + r1[1]) * inv1;
        }
    }
    __syncthreads();

    // ---- fused output projection: o = Wo v + bo ; y = 0.5 o + x ----
    {
        const int token = tid & 127;
        const int cs    = tid >> 7;          // 0..3, warp-uniform
        const int q     = blockIdx.x * 128 + token;

        float vr[Ex];
#pragma unroll
        for (int e = 0; e < Ex; e++) vr[e] = Vbuf[token * 33 + e];

        const float4* Wo4 = (const float4*)Wo;   // [Cx][Ex/4]
        const float* xp = x + (size_t)b * Cx * Nx + q;
        float* yp = out_y + (size_t)b * Cx * Nx + q;
        float* op = out_o ? (out_o + (size_t)b * Cx * Nx + q) : nullptr;

        const int c0 = cs * 64;
#pragma unroll 4
        for (int ci = 0; ci < 64; ci++) {
            const int c = c0 + ci;
            float a = bo[c];
#pragma unroll
            for (int e4 = 0; e4 < Ex / 4; e4++) {
                const float4 wv = Wo4[c * (Ex / 4) + e4];
                a += wv.x * vr[e4*4+0] + wv.y * vr[e4*4+1] +
                     wv.z * vr[e4*4+2] + wv.w * vr[e4*4+3];
            }
            if (op) op[c * Nx] = a;
            yp[c * Nx] = 0.5f * a + xp[c * Nx];
        }
    }

    if (out_gamma && blockIdx.x == 0 && blockIdx.y == 0 && tid == 0)
        out_gamma[0] = 0.5f;
}

// ===========================================================================
extern "C" void kernel_launch(void* const* d_in, const int* in_sizes, int n_in,
                              void* d_out, int out_size)
{
    const float* x  = (const float*)d_in[0];
    const float* Wk = (const float*)d_in[1];
    const float* bk = (const float*)d_in[2];
    const float* Wq = (const float*)d_in[3];
    const float* bq = (const float*)d_in[4];
    const float* Wv = (const float*)d_in[5];
    const float* bv = (const float*)d_in[6];
    const float* Wo = (const float*)d_in[7];
    const float* bo = (const float*)d_in[8];

    const size_t BCN = (size_t)Bx * Cx * Nx;  // 4194304
    float* out = (float*)d_out;

    const bool full = ((size_t)out_size >= 2 * BCN + 1);
    float* out_y = out;
    float* out_o = full ? (out + BCN) : nullptr;
    float* out_g = full ? (out + 2 * BCN) : nullptr;

    static bool attr_set = false;
    if (!attr_set) {
        cudaFuncSetAttribute(attn_mma_kernel,
                             cudaFuncAttributeMaxDynamicSharedMemorySize,
                             2 * BUFSZ);
        attr_set = true;
    }

    proj_kernel<<<dim3(Nx / 128, Bx, 3), 256>>>(x, Wk, bk, Wq, bq, Wv, bv);
    attn_mma_kernel<<<dim3(Nx / 128, Bx), 512, 2 * BUFSZ>>>(
        x, Wo, bo, out_y, out_o, out_g);
}

// round 17
// speedup vs baseline: 1.2123x; 1.0020x over previous
#include <cuda_runtime.h>
#include <cuda_bf16.h>
#include <cuda_fp16.h>
#include <cstdint>

#define Bx 4
#define Cx 256
#define Nx 4096
#define Ex 32
#define TK 128

// Scratch (allocation-free rule: __device__ globals).
__device__ float g_g[Bx * Ex * Nx];
__device__ unsigned short g_f16[(size_t)Bx * Nx * Ex];   // [b][n][e] fp16
__device__ unsigned short g_h16h[(size_t)Bx * Ex * Nx];  // [b][e][n] bf16 hi
__device__ unsigned short g_h16l[(size_t)Bx * Ex * Nx];  // [b][e][n] bf16 lo

// ---------------------------------------------------------------------------
__device__ __forceinline__ void mma_bf16(float* c, const uint32_t* a,
                                         uint32_t b0, uint32_t b1)
{
    asm volatile(
        "mma.sync.aligned.m16n8k16.row.col.f32.bf16.bf16.f32 "
        "{%0,%1,%2,%3},{%4,%5,%6,%7},{%8,%9},{%0,%1,%2,%3};\n"
        : "+f"(c[0]), "+f"(c[1]), "+f"(c[2]), "+f"(c[3])
        : "r"(a[0]), "r"(a[1]), "r"(a[2]), "r"(a[3]), "r"(b0), "r"(b1));
}

__device__ __forceinline__ void mma_f16(float* c, const uint32_t* a,
                                        uint32_t b0, uint32_t b1)
{
    asm volatile(
        "mma.sync.aligned.m16n8k16.row.col.f32.f16.f16.f32 "
        "{%0,%1,%2,%3},{%4,%5,%6,%7},{%8,%9},{%0,%1,%2,%3};\n"
        : "+f"(c[0]), "+f"(c[1]), "+f"(c[2]), "+f"(c[3])
        : "r"(a[0]), "r"(a[1]), "r"(a[2]), "r"(a[3]), "r"(b0), "r"(b1));
}

__device__ __forceinline__ void ldsm4(uint32_t addr, uint32_t* r)
{
    asm volatile("ldmatrix.sync.aligned.m8n8.x4.shared.b16 {%0,%1,%2,%3}, [%4];"
                 : "=r"(r[0]), "=r"(r[1]), "=r"(r[2]), "=r"(r[3]) : "r"(addr));
}

__device__ __forceinline__ uint32_t smem_u32(const void* p)
{
    uint32_t a;
    asm("{ .reg .u64 t; cvta.to.shared.u64 t, %1; cvt.u32.u64 %0, t; }"
        : "=r"(a) : "l"(p));
    return a;
}

__device__ __forceinline__ void cpasync16(uint32_t dst, const void* src)
{
    asm volatile("cp.async.cg.shared.global [%0], [%1], 16;\n"
                 :: "r"(dst), "l"(src) : "memory");
}

__device__ __forceinline__ void cpasync_commit()
{
    asm volatile("cp.async.commit_group;\n" ::: "memory");
}

template <int N>
__device__ __forceinline__ void cpasync_wait()
{
    asm volatile("cp.async.wait_group %0;\n" :: "n"(N) : "memory");
}

__device__ __forceinline__ float ex2(float x)
{
    float y;
    asm("ex2.approx.ftz.f32 %0, %1;" : "=f"(y) : "f"(x));
    return y;
}

__device__ __forceinline__ uint32_t packbf2(float a, float b)
{
    __nv_bfloat162 t = __float22bfloat162_rn(make_float2(a, b));
    return *(uint32_t*)&t;
}

__device__ __forceinline__ uint32_t packh2(float a, float b)
{
    __half2 t = __floats2half2_rn(a, b);
    return *(uint32_t*)&t;
}

// truncation split helpers for P (bf16): hi = top 16 bits, lo = p - hi
__device__ __forceinline__ uint32_t trunc_hi_pair(float p0, float p1)
{
    return __byte_perm(__float_as_uint(p0), __float_as_uint(p1), 0x7632);
}

__device__ __forceinline__ float trunc_lo(float p)
{
    return p - __uint_as_float(__float_as_uint(p) & 0xFFFF0000u);
}

// ===========================================================================
// Kernel 1: f/g/h = W @ x + b.  grid (32, B, 3), block 256.
// Round-17: x staged through smem (cp.async double buffer, 16-c chunks) so
// the 8 e-slices share one copy instead of 8 redundant LDG streams.
// Same FFMA order as before -> bit-identical outputs.
// ===========================================================================
__global__ __launch_bounds__(256) void proj_kernel(
    const float* __restrict__ x,
    const float* __restrict__ Wk, const float* __restrict__ bk,
    const float* __restrict__ Wq, const float* __restrict__ bq,
    const float* __restrict__ Wv, const float* __restrict__ bv)
{
    __shared__ __align__(16) float xs[2][16][128];   // 16 KB

    const int tid = threadIdx.x;
    const int tl  = tid & 31;
    const int es  = tid >> 5;           // 0..7, warp-uniform
    const int nb  = blockIdx.x * 128;
    const int n0  = nb + tl * 4;
    const int b   = blockIdx.y;
    const int z   = blockIdx.z;

    const float* W;
    const float* bias;
    if (z == 0)      { W = Wk; bias = bk; }
    else if (z == 1) { W = Wq; bias = bq; }
    else             { W = Wv; bias = bv; }

    const int e0 = es * 4;
    float acc[4][4];
#pragma unroll
    for (int e = 0; e < 4; e++) {
        const float bv0 = bias[e0 + e];
#pragma unroll
        for (int t = 0; t < 4; t++) acc[e][t] = bv0;
    }

    const float4* W4 = (const float4*)W;  // [Ex][Cx/4]

    // fill role: thread covers 8 floats of the [16 c][128 n] chunk
    const int fc  = tid >> 4;           // c row 0..15
    const int fp  = (tid & 15) * 8;     // n position
    const float* xsrc = x + (size_t)b * Cx * Nx + nb;
    const uint32_t xsD0 = smem_u32(&xs[0][fc][fp]);
    const uint32_t xsD1 = smem_u32(&xs[1][fc][fp]);

    // prefetch chunk 0
    {
        const float* s = xsrc + (size_t)fc * Nx + fp;
        cpasync16(xsD0, s);
        cpasync16(xsD0 + 16, s + 4);
        cpasync_commit();
    }

#pragma unroll 1
    for (int cc = 0; cc < 16; cc++) {
        const int buf = cc & 1;
        if (cc + 1 < 16) {
            const float* s = xsrc + (size_t)((cc + 1) * 16 + fc) * Nx + fp;
            const uint32_t d = (buf ? xsD0 : xsD1);
            cpasync16(d, s);
            cpasync16(d + 16, s + 4);
            cpasync_commit();
            cpasync_wait<1>();
        } else {
            cpasync_wait<0>();
        }
        __syncthreads();

#pragma unroll
        for (int c4 = 0; c4 < 4; c4++) {
            float4 xv[4];
#pragma unroll
            for (int j = 0; j < 4; j++)
                xv[j] = *(const float4*)&xs[buf][c4 * 4 + j][tl * 4];
#pragma unroll
            for (int e = 0; e < 4; e++) {
                const float4 w = W4[(e0 + e) * (Cx / 4) + cc * 4 + c4];
                acc[e][0] += w.x * xv[0].x + w.y * xv[1].x + w.z * xv[2].x + w.w * xv[3].x;
                acc[e][1] += w.x * xv[0].y + w.y * xv[1].y + w.z * xv[2].y + w.w * xv[3].y;
                acc[e][2] += w.x * xv[0].z + w.y * xv[1].z + w.z * xv[2].z + w.w * xv[3].z;
                acc[e][3] += w.x * xv[0].w + w.y * xv[1].w + w.z * xv[2].w + w.w * xv[3].w;
            }
        }
        __syncthreads();
    }

    if (z == 1) {
#pragma unroll
        for (int e = 0; e < 4; e++)
            *(float4*)&g_g[((size_t)b * Ex + e0 + e) * Nx + n0] =
                make_float4(acc[e][0], acc[e][1], acc[e][2], acc[e][3]);
    } else if (z == 0) {
        // f: [b][n][32] single fp16
#pragma unroll
        for (int t = 0; t < 4; t++) {
            const uint32_t h01 = packh2(acc[0][t], acc[1][t]);
            const uint32_t h23 = packh2(acc[2][t], acc[3][t]);
            const size_t base = ((size_t)b * Nx + (n0 + t)) * Ex + e0;
            *(uint2*)&g_f16[base] = make_uint2(h01, h23);
        }
    } else {
        // h: [b][e][n] bf16 hi/lo
#pragma unroll
        for (int e = 0; e < 4; e++) {
            const float v0 = acc[e][0], v1 = acc[e][1];
            const float v2 = acc[e][2], v3 = acc[e][3];
            const __nv_bfloat162 h01 = __float22bfloat162_rn(make_float2(v0, v1));
            const __nv_bfloat162 h23 = __float22bfloat162_rn(make_float2(v2, v3));
            const uint32_t l01 = packbf2(v0 - __bfloat162float(h01.x),
                                         v1 - __bfloat162float(h01.y));
            const uint32_t l23 = packbf2(v2 - __bfloat162float(h23.x),
                                         v3 - __bfloat162float(h23.y));
            const size_t base = ((size_t)b * Ex + (e0 + e)) * Nx + n0;
            *(uint2*)&g_h16h[base] = make_uint2(*(const uint32_t*)&h01,
                                                *(const uint32_t*)&h23);
            *(uint2*)&g_h16l[base] = make_uint2(l01, l23);
        }
    }
}

// ===========================================================================
// Kernel 2: flash attention + fused output projection.  [round-16, unchanged]
// S' = 2-pass fp16 (8 HMMA/kk); PV = 3-pass bf16 (12 HMMA/kk).
// 512 thr, 16 warps (qt, kh), cp.async double buffer, fused oproj.
// ===========================================================================
#define FROW 80      // bytes per fh row (40 fp16)
#define HROW 272     // bytes per hh row (136 bf16)
#define OFF_HH 10240
#define OFF_HL 18944
#define BUFSZ 27648

__global__ __launch_bounds__(512, 1) void attn_mma_kernel(
    const float* __restrict__ x,
    const float* __restrict__ Wo, const float* __restrict__ bo,
    float* __restrict__ out_y, float* __restrict__ out_o,
    float* __restrict__ out_gamma)
{
    extern __shared__ __align__(128) uint8_t S[];   // 2 * BUFSZ

    const int tid  = threadIdx.x;
    const int w    = tid >> 5;
    const int lane = tid & 31;
    const int qt   = w & 7;
    const int kh   = w >> 3;
    const int b    = blockIdx.y;
    const int qw   = blockIdx.x * 128 + qt * 16;

    const float* gb = g_g + (size_t)b * Ex * Nx;
    const unsigned short* fGg = g_f16 + (size_t)b * Nx * Ex;
    const unsigned short* hHg = g_h16h + (size_t)b * Ex * Nx;
    const unsigned short* hLg = g_h16l + (size_t)b * Ex * Nx;

    const uint32_t sBase = smem_u32(S);
    const float LOG2E = 1.4426950408889634f;

    // g in fp16 hi/lo (scaled by log2e)
    uint32_t gAh[2][4], gAl[2][4];
    {
        const int qa = qw + (lane >> 2);
#pragma unroll
        for (int ke = 0; ke < 2; ke++) {
#pragma unroll
            for (int r = 0; r < 4; r++) {
                const int row = qa + (r & 1) * 8;
                const int e   = ke * 16 + (r >> 1) * 8 + (lane & 3) * 2;
                const float v0 = gb[e * Nx + row] * LOG2E;
                const float v1 = gb[(e + 1) * Nx + row] * LOG2E;
                const __half h0 = __float2half_rn(v0);
                const __half h1 = __float2half_rn(v1);
                const __half2 hh2 = __halves2half2(h0, h1);
                gAh[ke][r] = *(const uint32_t*)&hh2;
                gAl[ke][r] = packh2(v0 - __half2float(h0),
                                    v1 - __half2float(h1));
            }
        }
    }

    float Vac[4][4];
#pragma unroll
    for (int nt = 0; nt < 4; nt++)
#pragma unroll
        for (int r = 0; r < 4; r++) Vac[nt][r] = 0.f;
    float lsum0 = 0.f, lsum1 = 0.f;

    const int m = lane >> 3;
    const uint32_t fSel = (uint32_t)(((m >> 1) * 8 + (lane & 7)) * FROW + (m & 1) * 16);
    const uint32_t hSel = (uint32_t)(((m >> 1) * 8 + (lane & 7)) * HROW + (m & 1) * 16);

    // per-thread fill roles (512 threads)
    const int fk = tid >> 2, fch = tid & 3;
    const int he = tid >> 4, hkc = (tid & 15) * 8;
    const uint32_t fOff = (uint32_t)(fk * FROW + fch * 16);
    const uint32_t hOff = (uint32_t)(he * HROW + hkc * 2);

    // issue fill for tile 0 into buffer 0
    {
        cpasync16(sBase + fOff,          fGg + (size_t)fk * Ex + fch * 8);
        cpasync16(sBase + OFF_HH + hOff, hHg + (size_t)he * Nx + hkc);
        cpasync16(sBase + OFF_HL + hOff, hLg + (size_t)he * Nx + hkc);
        cpasync_commit();
    }

#pragma unroll 1
    for (int t = 0; t < Nx / TK; t++) {
        const uint32_t cbuf = sBase + (uint32_t)(t & 1) * BUFSZ;

        if (t + 1 < Nx / TK) {
            const uint32_t nbuf = sBase + (uint32_t)((t + 1) & 1) * BUFSZ;
            const int i1 = (t + 1) * TK;
            cpasync16(nbuf + fOff,          fGg + (size_t)(i1 + fk) * Ex + fch * 8);
            cpasync16(nbuf + OFF_HH + hOff, hHg + (size_t)he * Nx + i1 + hkc);
            cpasync16(nbuf + OFF_HL + hOff, hLg + (size_t)he * Nx + i1 + hkc);
            cpasync_commit();
            cpasync_wait<1>();
        } else {
            cpasync_wait<0>();
        }
        __syncthreads();

        const uint32_t fhA = cbuf;
        const uint32_t hhA = cbuf + OFF_HH, hlA = cbuf + OFF_HL;

#pragma unroll 1
        for (int kk = 0; kk < 4; kk++) {
            const uint32_t fTile = (uint32_t)((kh * 64 + kk * 16) * FROW) + fSel;
            float c0a[4] = {0.f, 0.f, 0.f, 0.f};
            float c0b[4] = {0.f, 0.f, 0.f, 0.f};
            float c1a[4] = {0.f, 0.f, 0.f, 0.f};
            float c1b[4] = {0.f, 0.f, 0.f, 0.f};

            // S' : 2-pass fp16 (gh + gl) x f
#pragma unroll
            for (int ke = 0; ke < 2; ke++) {
                uint32_t bh[4];
                ldsm4(fhA + fTile + ke * 32, bh);
                mma_f16(c0a, gAh[ke], bh[0], bh[1]);
                mma_f16(c1a, gAh[ke], bh[2], bh[3]);
                mma_f16(c0b, gAl[ke], bh[0], bh[1]);
                mma_f16(c1b, gAl[ke], bh[2], bh[3]);
            }

            float p0[4], p1[4];
#pragma unroll
            for (int r = 0; r < 4; r++) {
                p0[r] = ex2(c0a[r] + c0b[r]);
                p1[r] = ex2(c1a[r] + c1b[r]);
            }
            lsum0 += (p0[0] + p0[1]) + (p1[0] + p1[1]);
            lsum1 += (p0[2] + p0[3]) + (p1[2] + p1[3]);

            // P: bf16 truncation split (range-safe)
            uint32_t aPh[4], aPl[4];
            aPh[0] = trunc_hi_pair(p0[0], p0[1]);
            aPh[1] = trunc_hi_pair(p0[2], p0[3]);
            aPh[2] = trunc_hi_pair(p1[0], p1[1]);
            aPh[3] = trunc_hi_pair(p1[2], p1[3]);
            aPl[0] = packbf2(trunc_lo(p0[0]), trunc_lo(p0[1]));
            aPl[1] = packbf2(trunc_lo(p0[2]), trunc_lo(p0[3]));
            aPl[2] = packbf2(trunc_lo(p1[0]), trunc_lo(p1[1]));
            aPl[3] = packbf2(trunc_lo(p1[2]), trunc_lo(p1[3]));

            // PV : 3-pass bf16
            const uint32_t hTile = (uint32_t)(kh * 128 + kk * 32) + hSel;
            uint32_t b0[4], b1[4], d0[4], d1[4];
            ldsm4(hhA + hTile, b0);
            ldsm4(hhA + hTile + 16 * HROW, b1);
            ldsm4(hlA + hTile, d0);
            ldsm4(hlA + hTile + 16 * HROW, d1);
#pragma unroll
            for (int j = 0; j < 2; j++) {
                mma_bf16(Vac[j],   aPh, b0[2*j], b0[2*j+1]);
                mma_bf16(Vac[j],   aPl, b0[2*j], b0[2*j+1]);
                mma_bf16(Vac[j],   aPh, d0[2*j], d0[2*j+1]);
                mma_bf16(Vac[2+j], aPh, b1[2*j], b1[2*j+1]);
                mma_bf16(Vac[2+j], aPl, b1[2*j], b1[2*j+1]);
                mma_bf16(Vac[2+j], aPh, d1[2*j], d1[2*j+1]);
            }
        }
        __syncthreads();
    }

    // ---- combine halves, normalize, leave v in smem ----
    float* Vbuf = (float*)S;               // [128][33] floats
    float* Lbuf = (float*)(S + 17408);     // 128 floats

    lsum0 += __shfl_xor_sync(0xffffffffu, lsum0, 1);
    lsum0 += __shfl_xor_sync(0xffffffffu, lsum0, 2);
    lsum1 += __shfl_xor_sync(0xffffffffu, lsum1, 1);
    lsum1 += __shfl_xor_sync(0xffffffffu, lsum1, 2);

    const int qrow = lane >> 2;
    if (kh == 1) {
#pragma unroll
        for (int nt = 0; nt < 4; nt++) {
            const int e = nt * 8 + (lane & 3) * 2;
            Vbuf[(qt * 16 + qrow) * 33 + e]         = Vac[nt][0];
            Vbuf[(qt * 16 + qrow) * 33 + e + 1]     = Vac[nt][1];
            Vbuf[(qt * 16 + qrow + 8) * 33 + e]     = Vac[nt][2];
            Vbuf[(qt * 16 + qrow + 8) * 33 + e + 1] = Vac[nt][3];
        }
        if ((lane & 3) == 0) {
            Lbuf[qt * 16 + qrow]     = lsum0;
            Lbuf[qt * 16 + qrow + 8] = lsum1;
        }
    }
    __syncthreads();
    if (kh == 0) {
        const float inv0 = 1.0f / (lsum0 + Lbuf[qt * 16 + qrow]);
        const float inv1 = 1.0f / (lsum1 + Lbuf[qt * 16 + qrow + 8]);
#pragma unroll
        for (int nt = 0; nt < 4; nt++) {
            const int e = nt * 8 + (lane & 3) * 2;
            float* r0 = &Vbuf[(qt * 16 + qrow) * 33 + e];
            float* r1 = &Vbuf[(qt * 16 + qrow + 8) * 33 + e];
            r0[0] = (Vac[nt][0] + r0[0]) * inv0;
            r0[1] = (Vac[nt][1] + r0[1]) * inv0;
            r1[0] = (Vac[nt][2] + r1[0]) * inv1;
            r1[1] = (Vac[nt][3] + r1[1]) * inv1;
        }
    }
    __syncthreads();

    // ---- fused output projection: o = Wo v + bo ; y = 0.5 o + x ----
    {
        const int token = tid & 127;
        const int cs    = tid >> 7;          // 0..3, warp-uniform
        const int q     = blockIdx.x * 128 + token;

        float vr[Ex];
#pragma unroll
        for (int e = 0; e < Ex; e++) vr[e] = Vbuf[token * 33 + e];

        const float4* Wo4 = (const float4*)Wo;   // [Cx][Ex/4]
        const float* xp = x + (size_t)b * Cx * Nx + q;
        float* yp = out_y + (size_t)b * Cx * Nx + q;
        float* op = out_o ? (out_o + (size_t)b * Cx * Nx + q) : nullptr;

        const int c0 = cs * 64;
#pragma unroll 4
        for (int ci = 0; ci < 64; ci++) {
            const int c = c0 + ci;
            float a = bo[c];
#pragma unroll
            for (int e4 = 0; e4 < Ex / 4; e4++) {
                const float4 wv = Wo4[c * (Ex / 4) + e4];
                a += wv.x * vr[e4*4+0] + wv.y * vr[e4*4+1] +
                     wv.z * vr[e4*4+2] + wv.w * vr[e4*4+3];
            }
            if (op) op[c * Nx] = a;
            yp[c * Nx] = 0.5f * a + xp[c * Nx];
        }
    }

    if (out_gamma && blockIdx.x == 0 && blockIdx.y == 0 && tid == 0)
        out_gamma[0] = 0.5f;
}

// ===========================================================================
extern "C" void kernel_launch(void* const* d_in, const int* in_sizes, int n_in,
                              void* d_out, int out_size)
{
    const float* x  = (const float*)d_in[0];
    const float* Wk = (const float*)d_in[1];
    const float* bk = (const float*)d_in[2];
    const float* Wq = (const float*)d_in[3];
    const float* bq = (const float*)d_in[4];
    const float* Wv = (const float*)d_in[5];
    const float* bv = (const float*)d_in[6];
    const float* Wo = (const float*)d_in[7];
    const float* bo = (const float*)d_in[8];

    const size_t BCN = (size_t)Bx * Cx * Nx;  // 4194304
    float* out = (float*)d_out;

    const bool full = ((size_t)out_size >= 2 * BCN + 1);
    float* out_y = out;
    float* out_o = full ? (out + BCN) : nullptr;
    float* out_g = full ? (out + 2 * BCN) : nullptr;

    static bool attr_set = false;
    if (!attr_set) {
        cudaFuncSetAttribute(attn_mma_kernel,
                             cudaFuncAttributeMaxDynamicSharedMemorySize,
                             2 * BUFSZ);
        attr_set = true;
    }

    proj_kernel<<<dim3(Nx / 128, Bx, 3), 256>>>(x, Wk, bk, Wq, bq, Wv, bv);
    attn_mma_kernel<<<dim3(Nx / 128, Bx), 512, 2 * BUFSZ>>>(
        x, Wo, bo, out_y, out_o, out_g);
}